// round 1
// baseline (speedup 1.0000x reference)
#include <cuda_runtime.h>

// Two-stage deterministic sum reduction over three fp32 arrays.
// Stage 1: grid of NBLK blocks, each block writes one partial to a
//          __device__ scratch array (fixed element->block mapping, so
//          partials are bitwise deterministic).
// Stage 2: single block reduces the NBLK partials in a fixed tree and
//          writes d_out[0].

#define NBLK 1184
#define NTHREADS 256

__device__ float g_partials[NBLK];

__device__ __forceinline__ float warp_reduce(float v) {
    #pragma unroll
    for (int off = 16; off > 0; off >>= 1)
        v += __shfl_down_sync(0xFFFFFFFFu, v, off);
    return v;
}

__global__ __launch_bounds__(NTHREADS) void sum3_stage1(
    const float4* __restrict__ a, int na4,
    const float4* __restrict__ b, int nb4,
    const float4* __restrict__ c, int nc4)
{
    const int tid = blockIdx.x * NTHREADS + threadIdx.x;
    const int stride = gridDim.x * NTHREADS;

    // 4 independent accumulators (one per float4 lane) for ILP.
    float s0 = 0.f, s1 = 0.f, s2 = 0.f, s3 = 0.f;

    for (int i = tid; i < na4; i += stride) {
        float4 v = __ldg(a + i);
        s0 += v.x; s1 += v.y; s2 += v.z; s3 += v.w;
    }
    for (int i = tid; i < nb4; i += stride) {
        float4 v = __ldg(b + i);
        s0 += v.x; s1 += v.y; s2 += v.z; s3 += v.w;
    }
    for (int i = tid; i < nc4; i += stride) {
        float4 v = __ldg(c + i);
        s0 += v.x; s1 += v.y; s2 += v.z; s3 += v.w;
    }

    float s = (s0 + s1) + (s2 + s3);

    // Block reduce: warp shuffle, then shared across warps.
    __shared__ float sh[NTHREADS / 32];
    s = warp_reduce(s);
    const int lane = threadIdx.x & 31;
    const int wid  = threadIdx.x >> 5;
    if (lane == 0) sh[wid] = s;
    __syncthreads();
    if (wid == 0) {
        float v = (lane < NTHREADS / 32) ? sh[lane] : 0.f;
        v = warp_reduce(v);
        if (lane == 0) g_partials[blockIdx.x] = v;
    }
}

__global__ __launch_bounds__(1024) void sum3_stage2(float* __restrict__ out)
{
    const int t = threadIdx.x;
    float s = 0.f;
    for (int i = t; i < NBLK; i += 1024)
        s += g_partials[i];

    __shared__ float sh[32];
    s = warp_reduce(s);
    const int lane = t & 31;
    const int wid  = t >> 5;
    if (lane == 0) sh[wid] = s;
    __syncthreads();
    if (wid == 0) {
        float v = (lane < 32) ? sh[lane] : 0.f;
        v = warp_reduce(v);
        if (lane == 0) out[0] = v;
    }
}

extern "C" void kernel_launch(void* const* d_in, const int* in_sizes, int n_in,
                              void* d_out, int out_size)
{
    const float4* a = (const float4*)d_in[0];
    const float4* b = (const float4*)d_in[1];
    const float4* c = (const float4*)d_in[2];
    const int na4 = in_sizes[0] / 4;
    const int nb4 = in_sizes[1] / 4;
    const int nc4 = in_sizes[2] / 4;

    sum3_stage1<<<NBLK, NTHREADS>>>(a, na4, b, nb4, c, nc4);
    sum3_stage2<<<1, 1024>>>((float*)d_out);
}

// round 2
// speedup vs baseline: 1.0484x; 1.0484x over previous
#include <cuda_runtime.h>

// Single-kernel deterministic sum over three fp32 arrays.
// Each block writes one partial; the last block to finish (int-counter
// threadfence pattern) reduces the partials and writes d_out[0], then
// resets the counter for graph replay. No float atomics -> deterministic.

#define NBLK 1184          // 148 SMs x 8 CTAs
#define NTHREADS 256

__device__ float g_partials[NBLK];
__device__ unsigned int g_count = 0;

__device__ __forceinline__ float warp_reduce(float v) {
    #pragma unroll
    for (int off = 16; off > 0; off >>= 1)
        v += __shfl_down_sync(0xFFFFFFFFu, v, off);
    return v;
}

__device__ __forceinline__ void accum_array(
    const float4* __restrict__ p, int n4, int tid, int stride,
    float& s0, float& s1, float& s2, float& s3)
{
    int i = tid;
    // 4x unrolled main loop: 4 independent 128-bit loads in flight.
    for (; i + 3 * stride < n4; i += 4 * stride) {
        float4 v0 = __ldg(p + i);
        float4 v1 = __ldg(p + i + stride);
        float4 v2 = __ldg(p + i + 2 * stride);
        float4 v3 = __ldg(p + i + 3 * stride);
        s0 += v0.x + v1.x + v2.x + v3.x;
        s1 += v0.y + v1.y + v2.y + v3.y;
        s2 += v0.z + v1.z + v2.z + v3.z;
        s3 += v0.w + v1.w + v2.w + v3.w;
    }
    for (; i < n4; i += stride) {
        float4 v = __ldg(p + i);
        s0 += v.x; s1 += v.y; s2 += v.z; s3 += v.w;
    }
}

__global__ __launch_bounds__(NTHREADS) void sum3_fused(
    const float4* __restrict__ a, int na4,
    const float4* __restrict__ b, int nb4,
    const float4* __restrict__ c, int nc4,
    float* __restrict__ out)
{
    const int tid = blockIdx.x * NTHREADS + threadIdx.x;
    const int stride = gridDim.x * NTHREADS;

    float s0 = 0.f, s1 = 0.f, s2 = 0.f, s3 = 0.f;
    accum_array(a, na4, tid, stride, s0, s1, s2, s3);
    accum_array(b, nb4, tid, stride, s0, s1, s2, s3);
    accum_array(c, nc4, tid, stride, s0, s1, s2, s3);

    float s = (s0 + s1) + (s2 + s3);

    // Block reduce.
    __shared__ float sh[NTHREADS / 32];
    s = warp_reduce(s);
    const int lane = threadIdx.x & 31;
    const int wid  = threadIdx.x >> 5;
    if (lane == 0) sh[wid] = s;
    __syncthreads();
    if (wid == 0) {
        float v = (lane < NTHREADS / 32) ? sh[lane] : 0.f;
        v = warp_reduce(v);
        if (lane == 0) g_partials[blockIdx.x] = v;
    }

    // Last-block-done detection (int counter, deterministic).
    __shared__ bool is_last;
    if (threadIdx.x == 0) {
        __threadfence();                      // partial visible before count
        unsigned int done = atomicAdd(&g_count, 1u);
        is_last = (done == (unsigned)(gridDim.x - 1));
    }
    __syncthreads();

    if (is_last) {
        // Reduce the NBLK partials in this block (fixed order -> deterministic).
        float t = 0.f;
        for (int i = threadIdx.x; i < NBLK; i += NTHREADS)
            t += __ldcg(&g_partials[i]);      // bypass L1: read fresh from L2
        t = warp_reduce(t);
        if (lane == 0) sh[wid] = t;
        __syncthreads();
        if (wid == 0) {
            float v = (lane < NTHREADS / 32) ? sh[lane] : 0.f;
            v = warp_reduce(v);
            if (lane == 0) {
                out[0] = v;
                g_count = 0;                  // reset for next graph replay
            }
        }
    }
}

extern "C" void kernel_launch(void* const* d_in, const int* in_sizes, int n_in,
                              void* d_out, int out_size)
{
    const float4* a = (const float4*)d_in[0];
    const float4* b = (const float4*)d_in[1];
    const float4* c = (const float4*)d_in[2];
    const int na4 = in_sizes[0] / 4;
    const int nb4 = in_sizes[1] / 4;
    const int nc4 = in_sizes[2] / 4;

    sum3_fused<<<NBLK, NTHREADS>>>(a, na4, b, nb4, c, nc4, (float*)d_out);
}